// round 14
// baseline (speedup 1.0000x reference)
#include <cuda_runtime.h>
#include <cuda_fp16.h>
#include <cuda_bf16.h>
#include <math.h>

#define NUM_LAYERS 2
#define B_SZ 2
#define S_TOTAL 13294
#define D_MODEL 256
#define NH 8
#define DH 32
#define NL 4
#define NP 4
#define DFF 1024
#define M_TOTAL (B_SZ * S_TOTAL)
#define PAD_M 26624            /* 208 * 128 */

__constant__ int c_H[4]     = {100, 50, 25, 13};
__constant__ int c_W[4]     = {100, 50, 25, 13};
__constant__ int c_start[4] = {0, 10000, 12500, 13125};

// ---------------- scratch (static device globals; no allocation) -------------
__device__ __align__(16) __half2 g_value_h[PAD_M * 128];  // value fp16 [row][128 half2]
__device__ __align__(16) __half  g_x16   [PAD_M * 256];   // fp16 copy of x (GEMM A)
__device__ __align__(16) __half2 g_msda16[PAD_M * 128];   // MSDA out fp16
__device__ __align__(16) __half  g_hid16 [PAD_M * DFF];   // FFN hidden fp16
__device__ __align__(16) float g_qk  [M_TOTAL * 384];     // packed [off(256) | attn(128)]
__device__ __align__(16) float g_tmp [M_TOTAL * D_MODEL];
__device__ __align__(16) float g_x   [M_TOTAL * D_MODEL];
__device__ float g_ref  [M_TOTAL * NL * 2];
// fp16 weights
__device__ __align__(16) __half g_wvqk16 [NUM_LAYERS * 256 * 640];  // packed val|off|attn
__device__ __align__(16) __half g_wout16 [NUM_LAYERS * 256 * 256];
__device__ __align__(16) __half g_w1_16  [NUM_LAYERS * 256 * 1024];
__device__ __align__(16) __half g_w2_16  [NUM_LAYERS * 1024 * 256];
__device__ __align__(16) float  g_bvqk   [NUM_LAYERS * 640];        // packed biases

// ---------------- fused fp32->fp16 conversion + packing (ONE launch) ---------
#define P0 65536    /* wval  -> packed col 0..255 */
#define P1 65536    /* woff  -> packed col 256..511 */
#define P2 32768    /* wattn -> packed col 512..639 */
#define P3 65536    /* wout   */
#define P4 262144   /* w1     */
#define P5 262144   /* w2     */
#define P6 3403264  /* src -> x16 */
#define P7 256      /* b_val  pack */
#define P8 256      /* b_off  pack */
#define P9 128      /* b_attn pack */
#define CVT_C0 (P0)
#define CVT_C1 (CVT_C0 + P1)
#define CVT_C2 (CVT_C1 + P2)
#define CVT_C3 (CVT_C2 + P3)
#define CVT_C4 (CVT_C3 + P4)
#define CVT_C5 (CVT_C4 + P5)
#define CVT_C6 (CVT_C5 + P6)
#define CVT_C7 (CVT_C6 + P7)
#define CVT_C8 (CVT_C7 + P8)
#define CVT_C9 (CVT_C8 + P9)

__global__ void cvt_all_kernel(const float* __restrict__ Wval, const float* __restrict__ Woff,
                               const float* __restrict__ Wattn, const float* __restrict__ Wout,
                               const float* __restrict__ W1w, const float* __restrict__ W2w,
                               const float* __restrict__ src, const float* __restrict__ bval,
                               const float* __restrict__ boff, const float* __restrict__ battn,
                               __half* __restrict__ wvqk16, __half* __restrict__ wout16,
                               __half* __restrict__ w1_16, __half* __restrict__ w2_16,
                               __half* __restrict__ x16, float* __restrict__ bvqk)
{
    int i = blockIdx.x * blockDim.x + threadIdx.x;   // pair index
    if (i >= CVT_C9) return;

    if (i < CVT_C0) {
        int e = i * 2;
        int l = e >> 16, rem = e & 65535, k = rem >> 8, c = rem & 255;
        float2 f = *(const float2*)(Wval + e);
        *(__half2*)(wvqk16 + (size_t)l * 163840 + k * 640 + c) = __floats2half2_rn(f.x, f.y);
    } else if (i < CVT_C1) {
        int e = (i - CVT_C0) * 2;
        int l = e >> 16, rem = e & 65535, k = rem >> 8, c = rem & 255;
        float2 f = *(const float2*)(Woff + e);
        *(__half2*)(wvqk16 + (size_t)l * 163840 + k * 640 + 256 + c) = __floats2half2_rn(f.x, f.y);
    } else if (i < CVT_C2) {
        int e = (i - CVT_C1) * 2;
        int l = e >> 15, rem = e & 32767, k = rem >> 7, c = rem & 127;
        float2 f = *(const float2*)(Wattn + e);
        *(__half2*)(wvqk16 + (size_t)l * 163840 + k * 640 + 512 + c) = __floats2half2_rn(f.x, f.y);
    } else if (i < CVT_C3) {
        int e = (i - CVT_C2) * 2;
        float2 f = *(const float2*)(Wout + e);
        *(__half2*)(wout16 + e) = __floats2half2_rn(f.x, f.y);
    } else if (i < CVT_C4) {
        int e = (i - CVT_C3) * 2;
        float2 f = *(const float2*)(W1w + e);
        *(__half2*)(w1_16 + e) = __floats2half2_rn(f.x, f.y);
    } else if (i < CVT_C5) {
        int e = (i - CVT_C4) * 2;
        float2 f = *(const float2*)(W2w + e);
        *(__half2*)(w2_16 + e) = __floats2half2_rn(f.x, f.y);
    } else if (i < CVT_C6) {
        int e = (i - CVT_C5) * 2;
        float2 f = *(const float2*)(src + e);
        *(__half2*)(x16 + e) = __floats2half2_rn(f.x, f.y);
    } else if (i < CVT_C7) {
        int e = (i - CVT_C6) * 2;
        int l = e >> 8, c = e & 255;
        bvqk[l * 640 + c]     = bval[e];
        bvqk[l * 640 + c + 1] = bval[e + 1];
    } else if (i < CVT_C8) {
        int e = (i - CVT_C7) * 2;
        int l = e >> 8, c = e & 255;
        bvqk[l * 640 + 256 + c]     = boff[e];
        bvqk[l * 640 + 256 + c + 1] = boff[e + 1];
    } else {
        int e = (i - CVT_C8) * 2;
        int l = e >> 7, c = e & 127;
        bvqk[l * 640 + 512 + c]     = battn[e];
        bvqk[l * 640 + 512 + c + 1] = battn[e + 1];
    }
}

// ---------------- reference points ------------------------------------------
__global__ void ref_kernel(const float* __restrict__ vr, float* __restrict__ ref)
{
    int idx = blockIdx.x * blockDim.x + threadIdx.x;
    if (idx >= B_SZ * S_TOTAL) return;
    int b = idx / S_TOTAL;
    int s = idx % S_TOTAL;

    int lvl = 0, rem = s;
    while (lvl < 3 && rem >= c_H[lvl] * c_W[lvl]) { rem -= c_H[lvl] * c_W[lvl]; lvl++; }
    int W_ = c_W[lvl], H_ = c_H[lvl];
    int i = rem / W_, j = rem % W_;

    float vrx = vr[(b * NL + lvl) * 2 + 0];
    float vry = vr[(b * NL + lvl) * 2 + 1];
    float bx = (j + 0.5f) / (vrx * (float)W_);
    float by = (i + 0.5f) / (vry * (float)H_);

    #pragma unroll
    for (int l = 0; l < NL; l++) {
        float vx = vr[(b * NL + l) * 2 + 0];
        float vy = vr[(b * NL + l) * 2 + 1];
        ref[((size_t)idx * NL + l) * 2 + 0] = bx * vx;
        ref[((size_t)idx * NL + l) * 2 + 1] = by * vy;
    }
}

// ---------------- FP16 GEMM: cp.async 3-stage + ldmatrix + m16n8k16 ----------
#define LDSM_X4(r0,r1,r2,r3,addr) \
    asm volatile("ldmatrix.sync.aligned.m8n8.x4.shared.b16 {%0,%1,%2,%3}, [%4];" \
        : "=r"(r0), "=r"(r1), "=r"(r2), "=r"(r3) : "r"(addr))

#define LDSM_X4_T(r0,r1,r2,r3,addr) \
    asm volatile("ldmatrix.sync.aligned.m8n8.x4.trans.shared.b16 {%0,%1,%2,%3}, [%4];" \
        : "=r"(r0), "=r"(r1), "=r"(r2), "=r"(r3) : "r"(addr))

#define MMA_F16(c0,c1,c2,c3, a0,a1,a2,a3, b0,b1) \
    asm volatile("mma.sync.aligned.m16n8k16.row.col.f32.f16.f16.f32 " \
        "{%0,%1,%2,%3},{%4,%5,%6,%7},{%8,%9},{%0,%1,%2,%3};" \
        : "+f"(c0), "+f"(c1), "+f"(c2), "+f"(c3) \
        : "r"(a0), "r"(a1), "r"(a2), "r"(a3), "r"(b0), "r"(b1))

#define CP_ASYNC16(smem_addr, gptr) \
    asm volatile("cp.async.cg.shared.global [%0], [%1], 16;" \
        :: "r"(smem_addr), "l"(gptr))

#define CP_COMMIT() asm volatile("cp.async.commit_group;")
#define CP_WAIT(n)  asm volatile("cp.async.wait_group %0;" :: "n"(n))

#define A_STRIDE 40
#define B_STRIDE 136
#define STAGES 3
#define SMEM_BYTES (STAGES * (128 * A_STRIDE + 32 * B_STRIDE) * 2)

// OUTMODE: 0 = float out, 1 = fp16 out + relu, 2 = fp16 out,
//          3 = split: cols [0,256) -> fp16 Ch (stride 256), cols [256,640) -> f32 C (stride 384)
template<int OUTMODE>
__global__ __launch_bounds__(256, 3)
void gemm_tc_kernel(const __half* __restrict__ A,
                    const __half* __restrict__ W,
                    const float* __restrict__ bias,
                    float* __restrict__ C,
                    __half2* __restrict__ Ch,
                    int M, int N, int K)
{
    extern __shared__ __align__(16) __half smem[];
    __half* AsBase = smem;
    __half* BsBase = smem + STAGES * 128 * A_STRIDE;

    const int bm = blockIdx.y * 128;
    const int bn = blockIdx.x * 128;
    const int tid  = threadIdx.x;
    const int lane = tid & 31;
    const int warp = tid >> 5;
    const int wm = (warp >> 2) * 64;
    const int wn = (warp & 3) * 32;

    const int arow = tid >> 1;
    const int aseg = (tid & 1) * 2;
    const int brow = tid >> 3;
    const int bseg = (tid & 7) * 2;

    float c[4][4][4];
    #pragma unroll
    for (int i = 0; i < 4; i++)
        #pragma unroll
        for (int j = 0; j < 4; j++)
            #pragma unroll
            for (int r = 0; r < 4; r++) c[i][j][r] = 0.f;

    const int NT = K >> 5;

    auto load_tile = [&](int stage, int k0) {
        const __half* ga = A + (size_t)(bm + arow) * K + k0 + aseg * 8;
        unsigned da = (unsigned)__cvta_generic_to_shared(
            AsBase + (stage * 128 + arow) * A_STRIDE + aseg * 8);
        CP_ASYNC16(da, ga);
        CP_ASYNC16(da + 16, ga + 8);
        const __half* gb = W + (size_t)(k0 + brow) * N + bn + bseg * 8;
        unsigned db = (unsigned)__cvta_generic_to_shared(
            BsBase + (stage * 32 + brow) * B_STRIDE + bseg * 8);
        CP_ASYNC16(db, gb);
        CP_ASYNC16(db + 16, gb + 8);
    };

    #pragma unroll
    for (int s = 0; s < STAGES - 1; s++) {
        if (s < NT) load_tile(s, s << 5);
        CP_COMMIT();
    }
    CP_WAIT(STAGES - 2);
    __syncthreads();

    for (int t = 0; t < NT; t++) {
        const int cur = t % STAGES;
        const __half* Acur = AsBase + cur * 128 * A_STRIDE;
        const __half* Bcur = BsBase + cur * 32 * B_STRIDE;

        int tn = t + STAGES - 1;
        if (tn < NT) load_tile(tn % STAGES, tn << 5);
        CP_COMMIT();

        #pragma unroll
        for (int kk = 0; kk < 32; kk += 16) {
            unsigned af[4][4], bf[4][2];
            #pragma unroll
            for (int mt = 0; mt < 4; mt++) {
                unsigned addr = (unsigned)__cvta_generic_to_shared(
                    Acur + (wm + mt * 16 + (lane & 15)) * A_STRIDE + kk + ((lane >> 4) << 3));
                LDSM_X4(af[mt][0], af[mt][1], af[mt][2], af[mt][3], addr);
            }
            #pragma unroll
            for (int ntp = 0; ntp < 2; ntp++) {
                unsigned addr = (unsigned)__cvta_generic_to_shared(
                    Bcur + (kk + (lane & 15)) * B_STRIDE + wn + ntp * 16 + ((lane >> 4) << 3));
                unsigned r0, r1, r2, r3;
                LDSM_X4_T(r0, r1, r2, r3, addr);
                bf[2 * ntp][0] = r0; bf[2 * ntp][1] = r1;
                bf[2 * ntp + 1][0] = r2; bf[2 * ntp + 1][1] = r3;
            }
            #pragma unroll
            for (int mt = 0; mt < 4; mt++)
                #pragma unroll
                for (int nt = 0; nt < 4; nt++)
                    MMA_F16(c[mt][nt][0], c[mt][nt][1], c[mt][nt][2], c[mt][nt][3],
                            af[mt][0], af[mt][1], af[mt][2], af[mt][3],
                            bf[nt][0], bf[nt][1]);
        }

        CP_WAIT(STAGES - 2);
        __syncthreads();
    }

    const int grow = lane >> 2;
    #pragma unroll
    for (int mt = 0; mt < 4; mt++) {
        int row0 = bm + wm + mt * 16 + grow;
        #pragma unroll
        for (int nt = 0; nt < 4; nt++) {
            int gn = bn + wn + nt * 8 + (lane & 3) * 2;
            float b0 = bias[gn], b1 = bias[gn + 1];
            float v0 = c[mt][nt][0] + b0;
            float v1 = c[mt][nt][1] + b1;
            float v2 = c[mt][nt][2] + b0;
            float v3 = c[mt][nt][3] + b1;
            if (OUTMODE == 1) {
                v0 = fmaxf(v0, 0.f); v1 = fmaxf(v1, 0.f);
                v2 = fmaxf(v2, 0.f); v3 = fmaxf(v3, 0.f);
            }
            if (OUTMODE == 3) {
                if (bn < 256) {   // value region: fp16 out, stride 256
                    if (row0 < M)
                        Ch[((size_t)row0 * 256 + gn) >> 1] = __floats2half2_rn(v0, v1);
                    if (row0 + 8 < M)
                        Ch[((size_t)(row0 + 8) * 256 + gn) >> 1] = __floats2half2_rn(v2, v3);
                } else {          // qk region: f32 out, stride 384
                    int col = gn - 256;
                    if (row0 < M)
                        *(float2*)(C + (size_t)row0 * 384 + col) = make_float2(v0, v1);
                    if (row0 + 8 < M)
                        *(float2*)(C + (size_t)(row0 + 8) * 384 + col) = make_float2(v2, v3);
                }
            } else if (OUTMODE >= 1) {
                if (row0 < M)
                    Ch[((size_t)row0 * N + gn) >> 1] = __floats2half2_rn(v0, v1);
                if (row0 + 8 < M)
                    Ch[((size_t)(row0 + 8) * N + gn) >> 1] = __floats2half2_rn(v2, v3);
            } else {
                if (row0 < M)
                    *(float2*)(C + (size_t)row0 * N + gn) = make_float2(v0, v1);
                if (row0 + 8 < M)
                    *(float2*)(C + (size_t)(row0 + 8) * N + gn) = make_float2(v2, v3);
            }
        }
    }
}

// ---------------- MSDA v4: 8 heads per warp, 16B gathers ---------------------
__global__ __launch_bounds__(256)
void msda_h_kernel(const __half2* __restrict__ value,
                   const float* __restrict__ qk,
                   const float* __restrict__ ref,
                   __half2* __restrict__ out)
{
    constexpr int kH[4]  = {100, 50, 25, 13};
    constexpr int kW[4]  = {100, 50, 25, 13};
    constexpr int kSt[4] = {0, 10000, 12500, 13125};

    int gwarp = (blockIdx.x * blockDim.x + threadIdx.x) >> 5;
    int lane  = threadIdx.x & 31;
    if (gwarp >= B_SZ * S_TOTAL) return;

    const int bq = gwarp;
    const int b  = (bq >= S_TOTAL) ? 1 : 0;
    const int h  = lane >> 2;
    const int q  = lane & 3;

    float4 lg = __ldg((const float4*)(qk + (size_t)bq * 384 + 256 + h * 16 + q * 4));
    float m = fmaxf(fmaxf(lg.x, lg.y), fmaxf(lg.z, lg.w));
    m = fmaxf(m, __shfl_xor_sync(0xffffffffu, m, 1));
    m = fmaxf(m, __shfl_xor_sync(0xffffffffu, m, 2));
    float e0 = __expf(lg.x - m), e1 = __expf(lg.y - m);
    float e2 = __expf(lg.z - m), e3 = __expf(lg.w - m);
    float ssum = e0 + e1 + e2 + e3;
    ssum += __shfl_xor_sync(0xffffffffu, ssum, 1);
    ssum += __shfl_xor_sync(0xffffffffu, ssum, 2);
    float inv = 1.f / ssum;
    float aw[4] = {e0 * inv, e1 * inv, e2 * inv, e3 * inv};

    const float4* offp = (const float4*)(qk + (size_t)bq * 384 + h * 32 + q * 8);
    float4 of0 = __ldg(offp);
    float4 of1 = __ldg(offp + 1);
    float offx[4] = {of0.x, of0.z, of1.x, of1.z};
    float offy[4] = {of0.y, of0.w, of1.y, of1.w};

    const float* refp = ref + (size_t)bq * (NL * 2);

    float2 acc[4];
    #pragma unroll
    for (int i = 0; i < 4; i++) acc[i] = make_float2(0.f, 0.f);

    #pragma unroll
    for (int l = 0; l < NL; l++) {
        const int H_ = kH[l], W_ = kW[l];
        const float fW = (float)W_, fH = (float)H_;
        const float invW = 1.f / fW, invH = 1.f / fH;
        float refx = __ldg(refp + l * 2 + 0);
        float refy = __ldg(refp + l * 2 + 1);
        const uint4* vbase = (const uint4*)(value + ((size_t)(b * S_TOTAL + kSt[l])) * 128 + h * 16 + q * 4);
        const int srclane = (lane & 28) | l;

        #pragma unroll
        for (int p = 0; p < NP; p++) {
            float w16 = __shfl_sync(0xffffffffu, aw[p],   srclane);
            float ox  = __shfl_sync(0xffffffffu, offx[p], srclane);
            float oy  = __shfl_sync(0xffffffffu, offy[p], srclane);

            float x = (refx + ox * invW) * fW - 0.5f;
            float y = (refy + oy * invH) * fH - 0.5f;
            float x0f = floorf(x), y0f = floorf(y);
            int x0 = (int)x0f, y0 = (int)y0f;
            float fx = x - x0f, fy = y - y0f;

            float mx0 = ((unsigned)x0     < (unsigned)W_) ? 1.f : 0.f;
            float mx1 = ((unsigned)(x0+1) < (unsigned)W_) ? 1.f : 0.f;
            float my0 = ((unsigned)y0     < (unsigned)H_) ? 1.f : 0.f;
            float my1 = ((unsigned)(y0+1) < (unsigned)H_) ? 1.f : 0.f;

            float gx1 = fx * mx1, gx0 = (1.f - fx) * mx0;
            float gy1 = fy * my1, gy0 = (1.f - fy) * my0;
            float w00 = gx0 * gy0 * w16, w10 = gx1 * gy0 * w16;
            float w01 = gx0 * gy1 * w16, w11 = gx1 * gy1 * w16;

            int cx0 = min(max(x0, 0), W_ - 1);
            int cx1 = min(max(x0 + 1, 0), W_ - 1);
            int cy0 = min(max(y0, 0), H_ - 1);
            int cy1 = min(max(y0 + 1, 0), H_ - 1);
            int r0 = cy0 * W_, r1 = cy1 * W_;

            uint4 u00 = __ldg(vbase + (size_t)(r0 + cx0) * 32);
            uint4 u10 = __ldg(vbase + (size_t)(r0 + cx1) * 32);
            uint4 u01 = __ldg(vbase + (size_t)(r1 + cx0) * 32);
            uint4 u11 = __ldg(vbase + (size_t)(r1 + cx1) * 32);

            const unsigned* p00 = &u00.x;
            const unsigned* p10 = &u10.x;
            const unsigned* p01 = &u01.x;
            const unsigned* p11 = &u11.x;
            #pragma unroll
            for (int j = 0; j < 4; j++) {
                float2 f00 = __half22float2(*(const __half2*)&p00[j]);
                float2 f10 = __half22float2(*(const __half2*)&p10[j]);
                float2 f01 = __half22float2(*(const __half2*)&p01[j]);
                float2 f11 = __half22float2(*(const __half2*)&p11[j]);
                acc[j].x = fmaf(w00, f00.x, fmaf(w10, f10.x, fmaf(w01, f01.x, fmaf(w11, f11.x, acc[j].x))));
                acc[j].y = fmaf(w00, f00.y, fmaf(w10, f10.y, fmaf(w01, f01.y, fmaf(w11, f11.y, acc[j].y))));
            }
        }
    }

    __half2 o[4];
    #pragma unroll
    for (int j = 0; j < 4; j++) o[j] = __floats2half2_rn(acc[j].x, acc[j].y);
    *(uint4*)(out + (size_t)bq * 128 + h * 16 + q * 4) = *(uint4*)o;
}

// -------- residual add + LayerNorm: one WARP per row, fp32 + fp16 out --------
__global__ __launch_bounds__(256)
void add_ln_kernel(const float* __restrict__ xin,
                   const float* __restrict__ r,
                   const float* __restrict__ g,
                   const float* __restrict__ bt,
                   float* __restrict__ xout,
                   __half* __restrict__ xout16)
{
    int gwarp = (blockIdx.x * blockDim.x + threadIdx.x) >> 5;
    int lane  = threadIdx.x & 31;
    if (gwarp >= M_TOTAL) return;
    const size_t base = (size_t)gwarp * 256 + lane * 8;

    float4 a0 = *(const float4*)(xin + base);
    float4 a1 = *(const float4*)(xin + base + 4);
    float4 r0 = *(const float4*)(r + base);
    float4 r1 = *(const float4*)(r + base + 4);
    float v[8] = {a0.x + r0.x, a0.y + r0.y, a0.z + r0.z, a0.w + r0.w,
                  a1.x + r1.x, a1.y + r1.y, a1.z + r1.z, a1.w + r1.w};

    float s1 = 0.f, s2 = 0.f;
    #pragma unroll
    for (int i = 0; i < 8; i++) { s1 += v[i]; s2 = fmaf(v[i], v[i], s2); }
    #pragma unroll
    for (int o = 16; o > 0; o >>= 1) {
        s1 += __shfl_xor_sync(0xffffffffu, s1, o);
        s2 += __shfl_xor_sync(0xffffffffu, s2, o);
    }
    float mean = s1 * (1.f / 256.f);
    float var  = s2 * (1.f / 256.f) - mean * mean;
    float inv  = rsqrtf(var + 1e-5f);

    float4 g0 = *(const float4*)(g + lane * 8);
    float4 g1 = *(const float4*)(g + lane * 8 + 4);
    float4 b0 = *(const float4*)(bt + lane * 8);
    float4 b1 = *(const float4*)(bt + lane * 8 + 4);
    float gg[8] = {g0.x, g0.y, g0.z, g0.w, g1.x, g1.y, g1.z, g1.w};
    float bb[8] = {b0.x, b0.y, b0.z, b0.w, b1.x, b1.y, b1.z, b1.w};

    float o[8];
    #pragma unroll
    for (int i = 0; i < 8; i++) o[i] = (v[i] - mean) * inv * gg[i] + bb[i];

    *(float4*)(xout + base)     = make_float4(o[0], o[1], o[2], o[3]);
    *(float4*)(xout + base + 4) = make_float4(o[4], o[5], o[6], o[7]);
    __half2 h[4] = {__floats2half2_rn(o[0], o[1]), __floats2half2_rn(o[2], o[3]),
                    __floats2half2_rn(o[4], o[5]), __floats2half2_rn(o[6], o[7])};
    *(uint4*)(xout16 + base) = *(uint4*)h;
}

// -----------------------------------------------------------------------------
extern "C" void kernel_launch(void* const* d_in, const int* in_sizes, int n_in,
                              void* d_out, int out_size)
{
    const float* src    = (const float*)d_in[0];
    const float* vr     = (const float*)d_in[2];
    const float* W_off  = (const float*)d_in[3];
    const float* b_off  = (const float*)d_in[4];
    const float* W_attn = (const float*)d_in[5];
    const float* b_attn = (const float*)d_in[6];
    const float* W_val  = (const float*)d_in[7];
    const float* b_val  = (const float*)d_in[8];
    const float* W_out  = (const float*)d_in[9];
    const float* b_out  = (const float*)d_in[10];
    const float* ln1_g  = (const float*)d_in[11];
    const float* ln1_b  = (const float*)d_in[12];
    const float* W1     = (const float*)d_in[13];
    const float* b1     = (const float*)d_in[14];
    const float* W2     = (const float*)d_in[15];
    const float* b2     = (const float*)d_in[16];
    const float* ln2_g  = (const float*)d_in[17];
    const float* ln2_b  = (const float*)d_in[18];

    __half2 *valueh, *msda16;
    __half *x16, *hid16, *wvqk16, *wout16, *w1_16, *w2_16;
    float *qk, *bvqk, *tmp, *xb, *refp;
    cudaGetSymbolAddress((void**)&valueh,  g_value_h);
    cudaGetSymbolAddress((void**)&msda16,  g_msda16);
    cudaGetSymbolAddress((void**)&x16,     g_x16);
    cudaGetSymbolAddress((void**)&hid16,   g_hid16);
    cudaGetSymbolAddress((void**)&wvqk16,  g_wvqk16);
    cudaGetSymbolAddress((void**)&wout16,  g_wout16);
    cudaGetSymbolAddress((void**)&w1_16,   g_w1_16);
    cudaGetSymbolAddress((void**)&w2_16,   g_w2_16);
    cudaGetSymbolAddress((void**)&qk,    g_qk);
    cudaGetSymbolAddress((void**)&bvqk,  g_bvqk);
    cudaGetSymbolAddress((void**)&tmp,   g_tmp);
    cudaGetSymbolAddress((void**)&xb,    g_x);
    cudaGetSymbolAddress((void**)&refp,  g_ref);

    cudaFuncSetAttribute(gemm_tc_kernel<0>, cudaFuncAttributeMaxDynamicSharedMemorySize, SMEM_BYTES);
    cudaFuncSetAttribute(gemm_tc_kernel<1>, cudaFuncAttributeMaxDynamicSharedMemorySize, SMEM_BYTES);
    cudaFuncSetAttribute(gemm_tc_kernel<2>, cudaFuncAttributeMaxDynamicSharedMemorySize, SMEM_BYTES);
    cudaFuncSetAttribute(gemm_tc_kernel<3>, cudaFuncAttributeMaxDynamicSharedMemorySize, SMEM_BYTES);

    const int M = M_TOTAL;
    const int GM = (M + 127) / 128;   // 208

    cvt_all_kernel<<<(CVT_C9 + 255) / 256, 256>>>(
        W_val, W_off, W_attn, W_out, W1, W2, src, b_val, b_off, b_attn,
        wvqk16, wout16, w1_16, w2_16, x16, bvqk);

    ref_kernel<<<(M + 255) / 256, 256>>>(vr, refp);

    for (int i = 0; i < NUM_LAYERS; i++) {
        const float* xin = (i == 0) ? src : xb;   // fp32 residual source

        // fused value + off + attn projection (N=640, split epilogue)
        gemm_tc_kernel<3><<<dim3(5, GM), 256, SMEM_BYTES>>>(
            x16, wvqk16 + (size_t)i * 256 * 640, bvqk + i * 640,
            qk, valueh, M, 640, 256);

        msda_h_kernel<<<(M * 32 + 255) / 256, 256>>>(valueh, qk, refp, msda16);

        gemm_tc_kernel<0><<<dim3(2, GM), 256, SMEM_BYTES>>>(
            (const __half*)msda16, wout16 + (size_t)i * 256 * 256, b_out + i * 256,
            tmp, nullptr, M, 256, 256);
        add_ln_kernel<<<(M * 32 + 255) / 256, 256>>>(xin, tmp, ln1_g + i * 256, ln1_b + i * 256, xb, x16);

        gemm_tc_kernel<1><<<dim3(8, GM), 256, SMEM_BYTES>>>(
            x16, w1_16 + (size_t)i * 256 * 1024, b1 + i * 1024,
            nullptr, (__half2*)hid16, M, 1024, 256);
        gemm_tc_kernel<0><<<dim3(2, GM), 256, SMEM_BYTES>>>(
            hid16, w2_16 + (size_t)i * 1024 * 256, b2 + i * 256,
            tmp, nullptr, M, 256, 1024);

        float* lnout = (i == NUM_LAYERS - 1) ? (float*)d_out : xb;
        add_ln_kernel<<<(M * 32 + 255) / 256, 256>>>(xb, tmp, ln2_g + i * 256, ln2_b + i * 256, lnout, x16);
    }
}

// round 15
// speedup vs baseline: 1.0990x; 1.0990x over previous
#include <cuda_runtime.h>
#include <cuda_fp16.h>
#include <cuda_bf16.h>
#include <math.h>

#define NUM_LAYERS 2
#define B_SZ 2
#define S_TOTAL 13294
#define D_MODEL 256
#define NH 8
#define DH 32
#define NL 4
#define NP 4
#define DFF 1024
#define M_TOTAL (B_SZ * S_TOTAL)
#define PAD_M 26624            /* 208 * 128 */

__constant__ int c_H[4]     = {100, 50, 25, 13};
__constant__ int c_W[4]     = {100, 50, 25, 13};
__constant__ int c_start[4] = {0, 10000, 12500, 13125};

// ---------------- scratch (static device globals; no allocation) -------------
__device__ __align__(16) __half2 g_value_h[PAD_M * 128];  // value fp16 [row][128 half2]
__device__ __align__(16) __half  g_x16   [PAD_M * 256];   // fp16 copy of x (GEMM A)
__device__ __align__(16) __half2 g_msda16[PAD_M * 128];   // MSDA out fp16
__device__ __align__(16) __half  g_hid16 [PAD_M * DFF];   // FFN hidden fp16
__device__ __align__(16) float g_qk  [M_TOTAL * 384];     // packed [off(256) | attn(128)]
__device__ __align__(16) float g_tmp [M_TOTAL * D_MODEL];
__device__ __align__(16) float g_x   [M_TOTAL * D_MODEL];
__device__ float g_ref  [M_TOTAL * NL * 2];
// fp16 weights
__device__ __align__(16) __half g_wval16 [NUM_LAYERS * 256 * 256];
__device__ __align__(16) __half g_wqk16  [NUM_LAYERS * 256 * 384];  // packed off|attn
__device__ __align__(16) __half g_wout16 [NUM_LAYERS * 256 * 256];
__device__ __align__(16) __half g_w1_16  [NUM_LAYERS * 256 * 1024];
__device__ __align__(16) __half g_w2_16  [NUM_LAYERS * 1024 * 256];
__device__ __align__(16) float  g_bqk    [NUM_LAYERS * 384];        // packed biases

// ---------------- fused fp32->fp16 conversion + packing (ONE launch) ---------
#define P0 65536    /* wval   */
#define P1 65536    /* woff -> packed */
#define P2 32768    /* wattn -> packed */
#define P3 65536    /* wout   */
#define P4 262144   /* w1     */
#define P5 262144   /* w2     */
#define P6 3403264  /* src -> x16 (M_TOTAL*128) */
#define P7 256      /* b_off pack (f32) */
#define P8 128      /* b_attn pack (f32) */
#define CVT_C0 (P0)
#define CVT_C1 (CVT_C0 + P1)
#define CVT_C2 (CVT_C1 + P2)
#define CVT_C3 (CVT_C2 + P3)
#define CVT_C4 (CVT_C3 + P4)
#define CVT_C5 (CVT_C4 + P5)
#define CVT_C6 (CVT_C5 + P6)
#define CVT_C7 (CVT_C6 + P7)
#define CVT_C8 (CVT_C7 + P8)

__global__ void cvt_all_kernel(const float* __restrict__ Wval, const float* __restrict__ Woff,
                               const float* __restrict__ Wattn, const float* __restrict__ Wout,
                               const float* __restrict__ W1w, const float* __restrict__ W2w,
                               const float* __restrict__ src, const float* __restrict__ boff,
                               const float* __restrict__ battn,
                               __half* __restrict__ wval16, __half* __restrict__ wqk16,
                               __half* __restrict__ wout16, __half* __restrict__ w1_16,
                               __half* __restrict__ w2_16, __half* __restrict__ x16,
                               float* __restrict__ bqk)
{
    int i = blockIdx.x * blockDim.x + threadIdx.x;   // pair index
    if (i >= CVT_C8) return;

    if (i < CVT_C0) {
        int e = i * 2;
        float2 f = *(const float2*)(Wval + e);
        *(__half2*)(wval16 + e) = __floats2half2_rn(f.x, f.y);
    } else if (i < CVT_C1) {
        int e = (i - CVT_C0) * 2;
        int l = e >> 16, rem = e & 65535, k = rem >> 8, c = rem & 255;
        float2 f = *(const float2*)(Woff + e);
        *(__half2*)(wqk16 + (size_t)l * 98304 + k * 384 + c) = __floats2half2_rn(f.x, f.y);
    } else if (i < CVT_C2) {
        int e = (i - CVT_C1) * 2;
        int l = e >> 15, rem = e & 32767, k = rem >> 7, c = rem & 127;
        float2 f = *(const float2*)(Wattn + e);
        *(__half2*)(wqk16 + (size_t)l * 98304 + k * 384 + 256 + c) = __floats2half2_rn(f.x, f.y);
    } else if (i < CVT_C3) {
        int e = (i - CVT_C2) * 2;
        float2 f = *(const float2*)(Wout + e);
        *(__half2*)(wout16 + e) = __floats2half2_rn(f.x, f.y);
    } else if (i < CVT_C4) {
        int e = (i - CVT_C3) * 2;
        float2 f = *(const float2*)(W1w + e);
        *(__half2*)(w1_16 + e) = __floats2half2_rn(f.x, f.y);
    } else if (i < CVT_C5) {
        int e = (i - CVT_C4) * 2;
        float2 f = *(const float2*)(W2w + e);
        *(__half2*)(w2_16 + e) = __floats2half2_rn(f.x, f.y);
    } else if (i < CVT_C6) {
        int e = (i - CVT_C5) * 2;
        float2 f = *(const float2*)(src + e);
        *(__half2*)(x16 + e) = __floats2half2_rn(f.x, f.y);
    } else if (i < CVT_C7) {
        int e = (i - CVT_C6) * 2;
        int l = e >> 8, c = e & 255;
        bqk[l * 384 + c]     = boff[e];
        bqk[l * 384 + c + 1] = boff[e + 1];
    } else {
        int e = (i - CVT_C7) * 2;
        int l = e >> 7, c = e & 127;
        bqk[l * 384 + 256 + c]     = battn[e];
        bqk[l * 384 + 256 + c + 1] = battn[e + 1];
    }
}

// ---------------- reference points ------------------------------------------
__global__ void ref_kernel(const float* __restrict__ vr, float* __restrict__ ref)
{
    int idx = blockIdx.x * blockDim.x + threadIdx.x;
    if (idx >= B_SZ * S_TOTAL) return;
    int b = idx / S_TOTAL;
    int s = idx % S_TOTAL;

    int lvl = 0, rem = s;
    while (lvl < 3 && rem >= c_H[lvl] * c_W[lvl]) { rem -= c_H[lvl] * c_W[lvl]; lvl++; }
    int W_ = c_W[lvl], H_ = c_H[lvl];
    int i = rem / W_, j = rem % W_;

    float vrx = vr[(b * NL + lvl) * 2 + 0];
    float vry = vr[(b * NL + lvl) * 2 + 1];
    float bx = (j + 0.5f) / (vrx * (float)W_);
    float by = (i + 0.5f) / (vry * (float)H_);

    #pragma unroll
    for (int l = 0; l < NL; l++) {
        float vx = vr[(b * NL + l) * 2 + 0];
        float vy = vr[(b * NL + l) * 2 + 1];
        ref[((size_t)idx * NL + l) * 2 + 0] = bx * vx;
        ref[((size_t)idx * NL + l) * 2 + 1] = by * vy;
    }
}

// ---------------- FP16 GEMM: cp.async 4-stage + ldmatrix + m16n8k16 ----------
#define LDSM_X4(r0,r1,r2,r3,addr) \
    asm volatile("ldmatrix.sync.aligned.m8n8.x4.shared.b16 {%0,%1,%2,%3}, [%4];" \
        : "=r"(r0), "=r"(r1), "=r"(r2), "=r"(r3) : "r"(addr))

#define LDSM_X4_T(r0,r1,r2,r3,addr) \
    asm volatile("ldmatrix.sync.aligned.m8n8.x4.trans.shared.b16 {%0,%1,%2,%3}, [%4];" \
        : "=r"(r0), "=r"(r1), "=r"(r2), "=r"(r3) : "r"(addr))

#define MMA_F16(c0,c1,c2,c3, a0,a1,a2,a3, b0,b1) \
    asm volatile("mma.sync.aligned.m16n8k16.row.col.f32.f16.f16.f32 " \
        "{%0,%1,%2,%3},{%4,%5,%6,%7},{%8,%9},{%0,%1,%2,%3};" \
        : "+f"(c0), "+f"(c1), "+f"(c2), "+f"(c3) \
        : "r"(a0), "r"(a1), "r"(a2), "r"(a3), "r"(b0), "r"(b1))

#define CP_ASYNC16(smem_addr, gptr) \
    asm volatile("cp.async.cg.shared.global [%0], [%1], 16;" \
        :: "r"(smem_addr), "l"(gptr))

#define CP_COMMIT() asm volatile("cp.async.commit_group;")
#define CP_WAIT(n)  asm volatile("cp.async.wait_group %0;" :: "n"(n))

#define A_STRIDE 40
#define B_STRIDE 136
#define STAGES 4
#define SMEM_BYTES (STAGES * (128 * A_STRIDE + 32 * B_STRIDE) * 2)

// OUTMODE: 0 = float out, 1 = fp16 out + relu, 2 = fp16 out
template<int OUTMODE>
__global__ __launch_bounds__(256)
void gemm_tc_kernel(const __half* __restrict__ A,
                    const __half* __restrict__ W,
                    const float* __restrict__ bias,
                    float* __restrict__ C,
                    __half2* __restrict__ Ch,
                    int M, int N, int K)
{
    extern __shared__ __align__(16) __half smem[];
    __half* AsBase = smem;
    __half* BsBase = smem + STAGES * 128 * A_STRIDE;

    const int bm = blockIdx.y * 128;
    const int bn = blockIdx.x * 128;
    const int tid  = threadIdx.x;
    const int lane = tid & 31;
    const int warp = tid >> 5;
    const int wm = (warp >> 2) * 64;
    const int wn = (warp & 3) * 32;

    const int arow = tid >> 1;
    const int aseg = (tid & 1) * 2;
    const int brow = tid >> 3;
    const int bseg = (tid & 7) * 2;

    float c[4][4][4];
    #pragma unroll
    for (int i = 0; i < 4; i++)
        #pragma unroll
        for (int j = 0; j < 4; j++)
            #pragma unroll
            for (int r = 0; r < 4; r++) c[i][j][r] = 0.f;

    const int NT = K >> 5;

    auto load_tile = [&](int stage, int k0) {
        const __half* ga = A + (size_t)(bm + arow) * K + k0 + aseg * 8;
        unsigned da = (unsigned)__cvta_generic_to_shared(
            AsBase + (stage * 128 + arow) * A_STRIDE + aseg * 8);
        CP_ASYNC16(da, ga);
        CP_ASYNC16(da + 16, ga + 8);
        const __half* gb = W + (size_t)(k0 + brow) * N + bn + bseg * 8;
        unsigned db = (unsigned)__cvta_generic_to_shared(
            BsBase + (stage * 32 + brow) * B_STRIDE + bseg * 8);
        CP_ASYNC16(db, gb);
        CP_ASYNC16(db + 16, gb + 8);
    };

    #pragma unroll
    for (int s = 0; s < STAGES - 1; s++) {
        if (s < NT) load_tile(s, s << 5);
        CP_COMMIT();
    }
    CP_WAIT(STAGES - 2);
    __syncthreads();

    for (int t = 0; t < NT; t++) {
        const int cur = t % STAGES;
        const __half* Acur = AsBase + cur * 128 * A_STRIDE;
        const __half* Bcur = BsBase + cur * 32 * B_STRIDE;

        int tn = t + STAGES - 1;
        if (tn < NT) load_tile(tn % STAGES, tn << 5);
        CP_COMMIT();

        #pragma unroll
        for (int kk = 0; kk < 32; kk += 16) {
            unsigned af[4][4], bf[4][2];
            #pragma unroll
            for (int mt = 0; mt < 4; mt++) {
                unsigned addr = (unsigned)__cvta_generic_to_shared(
                    Acur + (wm + mt * 16 + (lane & 15)) * A_STRIDE + kk + ((lane >> 4) << 3));
                LDSM_X4(af[mt][0], af[mt][1], af[mt][2], af[mt][3], addr);
            }
            #pragma unroll
            for (int ntp = 0; ntp < 2; ntp++) {
                unsigned addr = (unsigned)__cvta_generic_to_shared(
                    Bcur + (kk + (lane & 15)) * B_STRIDE + wn + ntp * 16 + ((lane >> 4) << 3));
                unsigned r0, r1, r2, r3;
                LDSM_X4_T(r0, r1, r2, r3, addr);
                bf[2 * ntp][0] = r0; bf[2 * ntp][1] = r1;
                bf[2 * ntp + 1][0] = r2; bf[2 * ntp + 1][1] = r3;
            }
            #pragma unroll
            for (int mt = 0; mt < 4; mt++)
                #pragma unroll
                for (int nt = 0; nt < 4; nt++)
                    MMA_F16(c[mt][nt][0], c[mt][nt][1], c[mt][nt][2], c[mt][nt][3],
                            af[mt][0], af[mt][1], af[mt][2], af[mt][3],
                            bf[nt][0], bf[nt][1]);
        }

        CP_WAIT(STAGES - 2);
        __syncthreads();
    }

    const int grow = lane >> 2;
    #pragma unroll
    for (int mt = 0; mt < 4; mt++) {
        int row0 = bm + wm + mt * 16 + grow;
        #pragma unroll
        for (int nt = 0; nt < 4; nt++) {
            int gn = bn + wn + nt * 8 + (lane & 3) * 2;
            float b0 = bias[gn], b1 = bias[gn + 1];
            float v0 = c[mt][nt][0] + b0;
            float v1 = c[mt][nt][1] + b1;
            float v2 = c[mt][nt][2] + b0;
            float v3 = c[mt][nt][3] + b1;
            if (OUTMODE == 1) {
                v0 = fmaxf(v0, 0.f); v1 = fmaxf(v1, 0.f);
                v2 = fmaxf(v2, 0.f); v3 = fmaxf(v3, 0.f);
            }
            if (OUTMODE >= 1) {
                if (row0 < M)
                    Ch[((size_t)row0 * N + gn) >> 1] = __floats2half2_rn(v0, v1);
                if (row0 + 8 < M)
                    Ch[((size_t)(row0 + 8) * N + gn) >> 1] = __floats2half2_rn(v2, v3);
            } else {
                if (row0 < M)
                    *(float2*)(C + (size_t)row0 * N + gn) = make_float2(v0, v1);
                if (row0 + 8 < M)
                    *(float2*)(C + (size_t)(row0 + 8) * N + gn) = make_float2(v2, v3);
            }
        }
    }
}

// ---------------- MSDA v5: 8 heads/warp, 16B gathers, HFMA2 blend ------------
// one warp per (b, q); lane = h*4 + q ; reads packed qk buffer [off(256)|attn(128)]
__global__ __launch_bounds__(256)
void msda_h_kernel(const __half2* __restrict__ value,
                   const float* __restrict__ qk,
                   const float* __restrict__ ref,
                   __half2* __restrict__ out)
{
    constexpr int kH[4]  = {100, 50, 25, 13};
    constexpr int kW[4]  = {100, 50, 25, 13};
    constexpr int kSt[4] = {0, 10000, 12500, 13125};

    int gwarp = (blockIdx.x * blockDim.x + threadIdx.x) >> 5;
    int lane  = threadIdx.x & 31;
    if (gwarp >= B_SZ * S_TOTAL) return;

    const int bq = gwarp;
    const int b  = (bq >= S_TOTAL) ? 1 : 0;
    const int h  = lane >> 2;     // head 0..7
    const int q  = lane & 3;      // channel-octet 0..3

    float4 lg = __ldg((const float4*)(qk + (size_t)bq * 384 + 256 + h * 16 + q * 4));
    float m = fmaxf(fmaxf(lg.x, lg.y), fmaxf(lg.z, lg.w));
    m = fmaxf(m, __shfl_xor_sync(0xffffffffu, m, 1));
    m = fmaxf(m, __shfl_xor_sync(0xffffffffu, m, 2));
    float e0 = __expf(lg.x - m), e1 = __expf(lg.y - m);
    float e2 = __expf(lg.z - m), e3 = __expf(lg.w - m);
    float ssum = e0 + e1 + e2 + e3;
    ssum += __shfl_xor_sync(0xffffffffu, ssum, 1);
    ssum += __shfl_xor_sync(0xffffffffu, ssum, 2);
    float inv = 1.f / ssum;
    float aw[4] = {e0 * inv, e1 * inv, e2 * inv, e3 * inv};

    const float4* offp = (const float4*)(qk + (size_t)bq * 384 + h * 32 + q * 8);
    float4 of0 = __ldg(offp);
    float4 of1 = __ldg(offp + 1);
    float offx[4] = {of0.x, of0.z, of1.x, of1.z};
    float offy[4] = {of0.y, of0.w, of1.y, of1.w};

    const float* refp = ref + (size_t)bq * (NL * 2);

    float2 acc[4];
    #pragma unroll
    for (int i = 0; i < 4; i++) acc[i] = make_float2(0.f, 0.f);

    #pragma unroll
    for (int l = 0; l < NL; l++) {
        const int H_ = kH[l], W_ = kW[l];
        const float fW = (float)W_, fH = (float)H_;
        const float invW = 1.f / fW, invH = 1.f / fH;
        float refx = __ldg(refp + l * 2 + 0);
        float refy = __ldg(refp + l * 2 + 1);
        const uint4* vbase = (const uint4*)(value + ((size_t)(b * S_TOTAL + kSt[l])) * 128 + h * 16 + q * 4);
        const int srclane = (lane & 28) | l;

        #pragma unroll
        for (int p = 0; p < NP; p++) {
            float w16 = __shfl_sync(0xffffffffu, aw[p],   srclane);
            float ox  = __shfl_sync(0xffffffffu, offx[p], srclane);
            float oy  = __shfl_sync(0xffffffffu, offy[p], srclane);

            float x = (refx + ox * invW) * fW - 0.5f;
            float y = (refy + oy * invH) * fH - 0.5f;
            float x0f = floorf(x), y0f = floorf(y);
            int x0 = (int)x0f, y0 = (int)y0f;
            float fx = x - x0f, fy = y - y0f;

            float mx0 = ((unsigned)x0     < (unsigned)W_) ? 1.f : 0.f;
            float mx1 = ((unsigned)(x0+1) < (unsigned)W_) ? 1.f : 0.f;
            float my0 = ((unsigned)y0     < (unsigned)H_) ? 1.f : 0.f;
            float my1 = ((unsigned)(y0+1) < (unsigned)H_) ? 1.f : 0.f;

            float gx1 = fx * mx1, gx0 = (1.f - fx) * mx0;
            float gy1 = fy * my1, gy0 = (1.f - fy) * my0;
            float w00 = gx0 * gy0 * w16, w10 = gx1 * gy0 * w16;
            float w01 = gx0 * gy1 * w16, w11 = gx1 * gy1 * w16;

            // pack weights to half2 once per sample (broadcast)
            __half2 hw00 = __float2half2_rn(w00);
            __half2 hw10 = __float2half2_rn(w10);
            __half2 hw01 = __float2half2_rn(w01);
            __half2 hw11 = __float2half2_rn(w11);

            int cx0 = min(max(x0, 0), W_ - 1);
            int cx1 = min(max(x0 + 1, 0), W_ - 1);
            int cy0 = min(max(y0, 0), H_ - 1);
            int cy1 = min(max(y0 + 1, 0), H_ - 1);
            int r0 = cy0 * W_, r1 = cy1 * W_;

            uint4 u00 = __ldg(vbase + (size_t)(r0 + cx0) * 32);
            uint4 u10 = __ldg(vbase + (size_t)(r0 + cx1) * 32);
            uint4 u01 = __ldg(vbase + (size_t)(r1 + cx0) * 32);
            uint4 u11 = __ldg(vbase + (size_t)(r1 + cx1) * 32);

            const unsigned* p00 = &u00.x;
            const unsigned* p10 = &u10.x;
            const unsigned* p01 = &u01.x;
            const unsigned* p11 = &u11.x;
            #pragma unroll
            for (int j = 0; j < 4; j++) {
                __half2 s = __hmul2(hw00, *(const __half2*)&p00[j]);
                s = __hfma2(hw10, *(const __half2*)&p10[j], s);
                s = __hfma2(hw01, *(const __half2*)&p01[j], s);
                s = __hfma2(hw11, *(const __half2*)&p11[j], s);
                float2 f = __half22float2(s);
                acc[j].x += f.x;
                acc[j].y += f.y;
            }
        }
    }

    __half2 o[4];
    #pragma unroll
    for (int j = 0; j < 4; j++) o[j] = __floats2half2_rn(acc[j].x, acc[j].y);
    *(uint4*)(out + (size_t)bq * 128 + h * 16 + q * 4) = *(uint4*)o;
}

// -------- residual add + LayerNorm: one WARP per row, fp32 + fp16 out --------
__global__ __launch_bounds__(256)
void add_ln_kernel(const float* __restrict__ xin,
                   const float* __restrict__ r,
                   const float* __restrict__ g,
                   const float* __restrict__ bt,
                   float* __restrict__ xout,
                   __half* __restrict__ xout16)
{
    int gwarp = (blockIdx.x * blockDim.x + threadIdx.x) >> 5;
    int lane  = threadIdx.x & 31;
    if (gwarp >= M_TOTAL) return;
    const size_t base = (size_t)gwarp * 256 + lane * 8;

    float4 a0 = *(const float4*)(xin + base);
    float4 a1 = *(const float4*)(xin + base + 4);
    float4 r0 = *(const float4*)(r + base);
    float4 r1 = *(const float4*)(r + base + 4);
    float v[8] = {a0.x + r0.x, a0.y + r0.y, a0.z + r0.z, a0.w + r0.w,
                  a1.x + r1.x, a1.y + r1.y, a1.z + r1.z, a1.w + r1.w};

    float s1 = 0.f, s2 = 0.f;
    #pragma unroll
    for (int i = 0; i < 8; i++) { s1 += v[i]; s2 = fmaf(v[i], v[i], s2); }
    #pragma unroll
    for (int o = 16; o > 0; o >>= 1) {
        s1 += __shfl_xor_sync(0xffffffffu, s1, o);
        s2 += __shfl_xor_sync(0xffffffffu, s2, o);
    }
    float mean = s1 * (1.f / 256.f);
    float var  = s2 * (1.f / 256.f) - mean * mean;
    float inv  = rsqrtf(var + 1e-5f);

    float4 g0 = *(const float4*)(g + lane * 8);
    float4 g1 = *(const float4*)(g + lane * 8 + 4);
    float4 b0 = *(const float4*)(bt + lane * 8);
    float4 b1 = *(const float4*)(bt + lane * 8 + 4);
    float gg[8] = {g0.x, g0.y, g0.z, g0.w, g1.x, g1.y, g1.z, g1.w};
    float bb[8] = {b0.x, b0.y, b0.z, b0.w, b1.x, b1.y, b1.z, b1.w};

    float o[8];
    #pragma unroll
    for (int i = 0; i < 8; i++) o[i] = (v[i] - mean) * inv * gg[i] + bb[i];

    *(float4*)(xout + base)     = make_float4(o[0], o[1], o[2], o[3]);
    *(float4*)(xout + base + 4) = make_float4(o[4], o[5], o[6], o[7]);
    __half2 h[4] = {__floats2half2_rn(o[0], o[1]), __floats2half2_rn(o[2], o[3]),
                    __floats2half2_rn(o[4], o[5]), __floats2half2_rn(o[6], o[7])};
    *(uint4*)(xout16 + base) = *(uint4*)h;
}

// -----------------------------------------------------------------------------
extern "C" void kernel_launch(void* const* d_in, const int* in_sizes, int n_in,
                              void* d_out, int out_size)
{
    const float* src    = (const float*)d_in[0];
    const float* vr     = (const float*)d_in[2];
    const float* W_off  = (const float*)d_in[3];
    const float* b_off  = (const float*)d_in[4];
    const float* W_attn = (const float*)d_in[5];
    const float* b_attn = (const float*)d_in[6];
    const float* W_val  = (const float*)d_in[7];
    const float* b_val  = (const float*)d_in[8];
    const float* W_out  = (const float*)d_in[9];
    const float* b_out  = (const float*)d_in[10];
    const float* ln1_g  = (const float*)d_in[11];
    const float* ln1_b  = (const float*)d_in[12];
    const float* W1     = (const float*)d_in[13];
    const float* b1     = (const float*)d_in[14];
    const float* W2     = (const float*)d_in[15];
    const float* b2     = (const float*)d_in[16];
    const float* ln2_g  = (const float*)d_in[17];
    const float* ln2_b  = (const float*)d_in[18];

    __half2 *valueh, *msda16;
    __half *x16, *hid16, *wval16, *wqk16, *wout16, *w1_16, *w2_16;
    float *qk, *bqk, *tmp, *xb, *refp;
    cudaGetSymbolAddress((void**)&valueh,  g_value_h);
    cudaGetSymbolAddress((void**)&msda16,  g_msda16);
    cudaGetSymbolAddress((void**)&x16,     g_x16);
    cudaGetSymbolAddress((void**)&hid16,   g_hid16);
    cudaGetSymbolAddress((void**)&wval16,  g_wval16);
    cudaGetSymbolAddress((void**)&wqk16,   g_wqk16);
    cudaGetSymbolAddress((void**)&wout16,  g_wout16);
    cudaGetSymbolAddress((void**)&w1_16,   g_w1_16);
    cudaGetSymbolAddress((void**)&w2_16,   g_w2_16);
    cudaGetSymbolAddress((void**)&qk,    g_qk);
    cudaGetSymbolAddress((void**)&bqk,   g_bqk);
    cudaGetSymbolAddress((void**)&tmp,   g_tmp);
    cudaGetSymbolAddress((void**)&xb,    g_x);
    cudaGetSymbolAddress((void**)&refp,  g_ref);

    cudaFuncSetAttribute(gemm_tc_kernel<0>, cudaFuncAttributeMaxDynamicSharedMemorySize, SMEM_BYTES);
    cudaFuncSetAttribute(gemm_tc_kernel<1>, cudaFuncAttributeMaxDynamicSharedMemorySize, SMEM_BYTES);
    cudaFuncSetAttribute(gemm_tc_kernel<2>, cudaFuncAttributeMaxDynamicSharedMemorySize, SMEM_BYTES);

    const int M = M_TOTAL;
    const int GM = (M + 127) / 128;   // 208

    cvt_all_kernel<<<(CVT_C8 + 255) / 256, 256>>>(
        W_val, W_off, W_attn, W_out, W1, W2, src, b_off, b_attn,
        wval16, wqk16, wout16, w1_16, w2_16, x16, bqk);

    ref_kernel<<<(M + 255) / 256, 256>>>(vr, refp);

    for (int i = 0; i < NUM_LAYERS; i++) {
        const float* xin = (i == 0) ? src : xb;   // fp32 residual source

        gemm_tc_kernel<2><<<dim3(2, GM), 256, SMEM_BYTES>>>(
            x16, wval16 + (size_t)i * 256 * 256, b_val + i * 256,
            nullptr, valueh, M, 256, 256);
        gemm_tc_kernel<0><<<dim3(3, GM), 256, SMEM_BYTES>>>(
            x16, wqk16 + (size_t)i * 256 * 384, bqk + i * 384,
            qk, nullptr, M, 384, 256);

        msda_h_kernel<<<(M * 32 + 255) / 256, 256>>>(valueh, qk, refp, msda16);

        gemm_tc_kernel<0><<<dim3(2, GM), 256, SMEM_BYTES>>>(
            (const __half*)msda16, wout16 + (size_t)i * 256 * 256, b_out + i * 256,
            tmp, nullptr, M, 256, 256);
        add_ln_kernel<<<(M * 32 + 255) / 256, 256>>>(xin, tmp, ln1_g + i * 256, ln1_b + i * 256, xb, x16);

        gemm_tc_kernel<1><<<dim3(8, GM), 256, SMEM_BYTES>>>(
            x16, w1_16 + (size_t)i * 256 * 1024, b1 + i * 1024,
            nullptr, (__half2*)hid16, M, 1024, 256);
        gemm_tc_kernel<0><<<dim3(2, GM), 256, SMEM_BYTES>>>(
            hid16, w2_16 + (size_t)i * 1024 * 256, b2 + i * 256,
            tmp, nullptr, M, 256, 1024);

        float* lnout = (i == NUM_LAYERS - 1) ? (float*)d_out : xb;
        add_ln_kernel<<<(M * 32 + 255) / 256, 256>>>(xb, tmp, ln2_g + i * 256, ln2_b + i * 256, lnout, x16);
    }
}

// round 17
// speedup vs baseline: 1.1835x; 1.0768x over previous
#include <cuda_runtime.h>
#include <cuda_fp16.h>
#include <cuda_bf16.h>
#include <math.h>

#define NUM_LAYERS 2
#define B_SZ 2
#define S_TOTAL 13294
#define D_MODEL 256
#define NH 8
#define DH 32
#define NL 4
#define NP 4
#define DFF 1024
#define M_TOTAL (B_SZ * S_TOTAL)
#define PAD_M 26624            /* 208 * 128 */

__constant__ int c_H[4]     = {100, 50, 25, 13};
__constant__ int c_W[4]     = {100, 50, 25, 13};
__constant__ int c_start[4] = {0, 10000, 12500, 13125};

// ---------------- scratch (static device globals; no allocation) -------------
__device__ __align__(16) __half2 g_value_h[PAD_M * 128];  // value fp16 [row][128 half2]
__device__ __align__(16) __half  g_x16   [PAD_M * 256];   // fp16 copy of x (GEMM A)
__device__ __align__(16) __half2 g_msda16[PAD_M * 128];   // MSDA out fp16
__device__ __align__(16) __half  g_hid16 [PAD_M * DFF];   // FFN hidden fp16
__device__ __align__(16) float g_qk  [M_TOTAL * 384];     // packed [off(256) | attn(128)]
__device__ __align__(16) float g_tmp [M_TOTAL * D_MODEL];
__device__ __align__(16) float g_x   [M_TOTAL * D_MODEL];
__device__ float g_ref  [M_TOTAL * NL * 2];
// fp16 weights
__device__ __align__(16) __half g_wvqk16 [NUM_LAYERS * 256 * 640];  // packed val|off|attn
__device__ __align__(16) __half g_wout16 [NUM_LAYERS * 256 * 256];
__device__ __align__(16) __half g_w1_16  [NUM_LAYERS * 256 * 1024];
__device__ __align__(16) __half g_w2_16  [NUM_LAYERS * 1024 * 256];
__device__ __align__(16) float  g_bvqk   [NUM_LAYERS * 640];        // packed biases

// ---------------- fused fp32->fp16 conversion + packing (ONE launch) ---------
#define P0 65536    /* wval  -> packed col 0..255 */
#define P1 65536    /* woff  -> packed col 256..511 */
#define P2 32768    /* wattn -> packed col 512..639 */
#define P3 65536    /* wout   */
#define P4 262144   /* w1     */
#define P5 262144   /* w2     */
#define P6 3403264  /* src -> x16 */
#define P7 256      /* b_val  pack */
#define P8 256      /* b_off  pack */
#define P9 128      /* b_attn pack */
#define CVT_C0 (P0)
#define CVT_C1 (CVT_C0 + P1)
#define CVT_C2 (CVT_C1 + P2)
#define CVT_C3 (CVT_C2 + P3)
#define CVT_C4 (CVT_C3 + P4)
#define CVT_C5 (CVT_C4 + P5)
#define CVT_C6 (CVT_C5 + P6)
#define CVT_C7 (CVT_C6 + P7)
#define CVT_C8 (CVT_C7 + P8)
#define CVT_C9 (CVT_C8 + P9)

__global__ void cvt_all_kernel(const float* __restrict__ Wval, const float* __restrict__ Woff,
                               const float* __restrict__ Wattn, const float* __restrict__ Wout,
                               const float* __restrict__ W1w, const float* __restrict__ W2w,
                               const float* __restrict__ src, const float* __restrict__ bval,
                               const float* __restrict__ boff, const float* __restrict__ battn,
                               __half* __restrict__ wvqk16, __half* __restrict__ wout16,
                               __half* __restrict__ w1_16, __half* __restrict__ w2_16,
                               __half* __restrict__ x16, float* __restrict__ bvqk)
{
    int i = blockIdx.x * blockDim.x + threadIdx.x;   // pair index
    if (i >= CVT_C9) return;

    if (i < CVT_C0) {
        int e = i * 2;
        int l = e >> 16, rem = e & 65535, k = rem >> 8, c = rem & 255;
        float2 f = *(const float2*)(Wval + e);
        *(__half2*)(wvqk16 + (size_t)l * 163840 + k * 640 + c) = __floats2half2_rn(f.x, f.y);
    } else if (i < CVT_C1) {
        int e = (i - CVT_C0) * 2;
        int l = e >> 16, rem = e & 65535, k = rem >> 8, c = rem & 255;
        float2 f = *(const float2*)(Woff + e);
        *(__half2*)(wvqk16 + (size_t)l * 163840 + k * 640 + 256 + c) = __floats2half2_rn(f.x, f.y);
    } else if (i < CVT_C2) {
        int e = (i - CVT_C1) * 2;
        int l = e >> 15, rem = e & 32767, k = rem >> 7, c = rem & 127;
        float2 f = *(const float2*)(Wattn + e);
        *(__half2*)(wvqk16 + (size_t)l * 163840 + k * 640 + 512 + c) = __floats2half2_rn(f.x, f.y);
    } else if (i < CVT_C3) {
        int e = (i - CVT_C2) * 2;
        float2 f = *(const float2*)(Wout + e);
        *(__half2*)(wout16 + e) = __floats2half2_rn(f.x, f.y);
    } else if (i < CVT_C4) {
        int e = (i - CVT_C3) * 2;
        float2 f = *(const float2*)(W1w + e);
        *(__half2*)(w1_16 + e) = __floats2half2_rn(f.x, f.y);
    } else if (i < CVT_C5) {
        int e = (i - CVT_C4) * 2;
        float2 f = *(const float2*)(W2w + e);
        *(__half2*)(w2_16 + e) = __floats2half2_rn(f.x, f.y);
    } else if (i < CVT_C6) {
        int e = (i - CVT_C5) * 2;
        float2 f = *(const float2*)(src + e);
        *(__half2*)(x16 + e) = __floats2half2_rn(f.x, f.y);
    } else if (i < CVT_C7) {
        int e = (i - CVT_C6) * 2;
        int l = e >> 8, c = e & 255;
        bvqk[l * 640 + c]     = bval[e];
        bvqk[l * 640 + c + 1] = bval[e + 1];
    } else if (i < CVT_C8) {
        int e = (i - CVT_C7) * 2;
        int l = e >> 8, c = e & 255;
        bvqk[l * 640 + 256 + c]     = boff[e];
        bvqk[l * 640 + 256 + c + 1] = boff[e + 1];
    } else {
        int e = (i - CVT_C8) * 2;
        int l = e >> 7, c = e & 127;
        bvqk[l * 640 + 512 + c]     = battn[e];
        bvqk[l * 640 + 512 + c + 1] = battn[e + 1];
    }
}

// ---------------- reference points ------------------------------------------
__global__ void ref_kernel(const float* __restrict__ vr, float* __restrict__ ref)
{
    int idx = blockIdx.x * blockDim.x + threadIdx.x;
    if (idx >= B_SZ * S_TOTAL) return;
    int b = idx / S_TOTAL;
    int s = idx % S_TOTAL;

    int lvl = 0, rem = s;
    while (lvl < 3 && rem >= c_H[lvl] * c_W[lvl]) { rem -= c_H[lvl] * c_W[lvl]; lvl++; }
    int W_ = c_W[lvl], H_ = c_H[lvl];
    int i = rem / W_, j = rem % W_;

    float vrx = vr[(b * NL + lvl) * 2 + 0];
    float vry = vr[(b * NL + lvl) * 2 + 1];
    float bx = (j + 0.5f) / (vrx * (float)W_);
    float by = (i + 0.5f) / (vry * (float)H_);

    #pragma unroll
    for (int l = 0; l < NL; l++) {
        float vx = vr[(b * NL + l) * 2 + 0];
        float vy = vr[(b * NL + l) * 2 + 1];
        ref[((size_t)idx * NL + l) * 2 + 0] = bx * vx;
        ref[((size_t)idx * NL + l) * 2 + 1] = by * vy;
    }
}

// ---------------- FP16 GEMM: cp.async 4-stage + ldmatrix + m16n8k16 ----------
// fragment double-buffered mainloop
#define LDSM_X4(r0,r1,r2,r3,addr) \
    asm volatile("ldmatrix.sync.aligned.m8n8.x4.shared.b16 {%0,%1,%2,%3}, [%4];" \
        : "=r"(r0), "=r"(r1), "=r"(r2), "=r"(r3) : "r"(addr))

#define LDSM_X4_T(r0,r1,r2,r3,addr) \
    asm volatile("ldmatrix.sync.aligned.m8n8.x4.trans.shared.b16 {%0,%1,%2,%3}, [%4];" \
        : "=r"(r0), "=r"(r1), "=r"(r2), "=r"(r3) : "r"(addr))

#define MMA_F16(c0,c1,c2,c3, a0,a1,a2,a3, b0,b1) \
    asm volatile("mma.sync.aligned.m16n8k16.row.col.f32.f16.f16.f32 " \
        "{%0,%1,%2,%3},{%4,%5,%6,%7},{%8,%9},{%0,%1,%2,%3};" \
        : "+f"(c0), "+f"(c1), "+f"(c2), "+f"(c3) \
        : "r"(a0), "r"(a1), "r"(a2), "r"(a3), "r"(b0), "r"(b1))

#define CP_ASYNC16(smem_addr, gptr) \
    asm volatile("cp.async.cg.shared.global [%0], [%1], 16;" \
        :: "r"(smem_addr), "l"(gptr))

#define CP_COMMIT() asm volatile("cp.async.commit_group;")
#define CP_WAIT(n)  asm volatile("cp.async.wait_group %0;" :: "n"(n))

#define A_STRIDE 40
#define B_STRIDE 136
#define STAGES 4
#define SMEM_BYTES (STAGES * (128 * A_STRIDE + 32 * B_STRIDE) * 2)

// OUTMODE: 0 = float out, 1 = fp16 out + relu, 2 = fp16 out,
//          3 = split: cols [0,256) -> fp16 Ch (stride 256), cols [256,640) -> f32 C (stride 384)
template<int OUTMODE>
__global__ __launch_bounds__(256)
void gemm_tc_kernel(const __half* __restrict__ A,
                    const __half* __restrict__ W,
                    const float* __restrict__ bias,
                    float* __restrict__ C,
                    __half2* __restrict__ Ch,
                    int M, int N, int K)
{
    extern __shared__ __align__(16) __half smem[];
    __half* AsBase = smem;
    __half* BsBase = smem + STAGES * 128 * A_STRIDE;

    const int bm = blockIdx.y * 128;
    const int bn = blockIdx.x * 128;
    const int tid  = threadIdx.x;
    const int lane = tid & 31;
    const int warp = tid >> 5;
    const int wm = (warp >> 2) * 64;
    const int wn = (warp & 3) * 32;

    const int arow = tid >> 1;
    const int aseg = (tid & 1) * 2;
    const int brow = tid >> 3;
    const int bseg = (tid & 7) * 2;

    float c[4][4][4];
    #pragma unroll
    for (int i = 0; i < 4; i++)
        #pragma unroll
        for (int j = 0; j < 4; j++)
            #pragma unroll
            for (int r = 0; r < 4; r++) c[i][j][r] = 0.f;

    const int NT = K >> 5;

    auto load_tile = [&](int stage, int k0) {
        const __half* ga = A + (size_t)(bm + arow) * K + k0 + aseg * 8;
        unsigned da = (unsigned)__cvta_generic_to_shared(
            AsBase + (stage * 128 + arow) * A_STRIDE + aseg * 8);
        CP_ASYNC16(da, ga);
        CP_ASYNC16(da + 16, ga + 8);
        const __half* gb = W + (size_t)(k0 + brow) * N + bn + bseg * 8;
        unsigned db = (unsigned)__cvta_generic_to_shared(
            BsBase + (stage * 32 + brow) * B_STRIDE + bseg * 8);
        CP_ASYNC16(db, gb);
        CP_ASYNC16(db + 16, gb + 8);
    };

    // fragment loader for one kk-half of a stage
    auto load_frags = [&](int stage, int kk, unsigned af[4][4], unsigned bf[4][2]) {
        const __half* Acur = AsBase + stage * 128 * A_STRIDE;
        const __half* Bcur = BsBase + stage * 32 * B_STRIDE;
        #pragma unroll
        for (int mt = 0; mt < 4; mt++) {
            unsigned addr = (unsigned)__cvta_generic_to_shared(
                Acur + (wm + mt * 16 + (lane & 15)) * A_STRIDE + kk + ((lane >> 4) << 3));
            LDSM_X4(af[mt][0], af[mt][1], af[mt][2], af[mt][3], addr);
        }
        #pragma unroll
        for (int ntp = 0; ntp < 2; ntp++) {
            unsigned addr = (unsigned)__cvta_generic_to_shared(
                Bcur + (kk + (lane & 15)) * B_STRIDE + wn + ntp * 16 + ((lane >> 4) << 3));
            unsigned r0, r1, r2, r3;
            LDSM_X4_T(r0, r1, r2, r3, addr);
            bf[2 * ntp][0] = r0; bf[2 * ntp][1] = r1;
            bf[2 * ntp + 1][0] = r2; bf[2 * ntp + 1][1] = r3;
        }
    };
    auto mma_block = [&](unsigned af[4][4], unsigned bf[4][2]) {
        #pragma unroll
        for (int mt = 0; mt < 4; mt++)
            #pragma unroll
            for (int nt = 0; nt < 4; nt++)
                MMA_F16(c[mt][nt][0], c[mt][nt][1], c[mt][nt][2], c[mt][nt][3],
                        af[mt][0], af[mt][1], af[mt][2], af[mt][3],
                        bf[nt][0], bf[nt][1]);
    };

    #pragma unroll
    for (int s = 0; s < STAGES - 1; s++) {
        if (s < NT) load_tile(s, s << 5);
        CP_COMMIT();
    }
    CP_WAIT(STAGES - 2);
    __syncthreads();

    unsigned afA[4][4], bfA[4][2], afB[4][4], bfB[4][2];
    load_frags(0, 0, afA, bfA);   // first half of tile 0

    for (int t = 0; t < NT; t++) {
        const int cur = t % STAGES;

        // issue DMA for stage t+STAGES-1
        int tn = t + STAGES - 1;
        if (tn < NT) load_tile(tn % STAGES, tn << 5);
        CP_COMMIT();

        // prefetch second half fragments, then compute first half
        load_frags(cur, 16, afB, bfB);
        mma_block(afA, bfA);
        mma_block(afB, bfB);

        CP_WAIT(STAGES - 2);
        __syncthreads();
        if (t + 1 < NT)
            load_frags((t + 1) % STAGES, 0, afA, bfA);   // first half of next tile
    }

    const int grow = lane >> 2;
    #pragma unroll
    for (int mt = 0; mt < 4; mt++) {
        int row0 = bm + wm + mt * 16 + grow;
        #pragma unroll
        for (int nt = 0; nt < 4; nt++) {
            int gn = bn + wn + nt * 8 + (lane & 3) * 2;
            float b0 = bias[gn], b1 = bias[gn + 1];
            float v0 = c[mt][nt][0] + b0;
            float v1 = c[mt][nt][1] + b1;
            float v2 = c[mt][nt][2] + b0;
            float v3 = c[mt][nt][3] + b1;
            if (OUTMODE == 1) {
                v0 = fmaxf(v0, 0.f); v1 = fmaxf(v1, 0.f);
                v2 = fmaxf(v2, 0.f); v3 = fmaxf(v3, 0.f);
            }
            if (OUTMODE == 3) {
                if (bn < 256) {   // value region: fp16 out, stride 256
                    if (row0 < M)
                        Ch[((size_t)row0 * 256 + gn) >> 1] = __floats2half2_rn(v0, v1);
                    if (row0 + 8 < M)
                        Ch[((size_t)(row0 + 8) * 256 + gn) >> 1] = __floats2half2_rn(v2, v3);
                } else {          // qk region: f32 out, stride 384
                    int col = gn - 256;
                    if (row0 < M)
                        *(float2*)(C + (size_t)row0 * 384 + col) = make_float2(v0, v1);
                    if (row0 + 8 < M)
                        *(float2*)(C + (size_t)(row0 + 8) * 384 + col) = make_float2(v2, v3);
                }
            } else if (OUTMODE >= 1) {
                if (row0 < M)
                    Ch[((size_t)row0 * N + gn) >> 1] = __floats2half2_rn(v0, v1);
                if (row0 + 8 < M)
                    Ch[((size_t)(row0 + 8) * N + gn) >> 1] = __floats2half2_rn(v2, v3);
            } else {
                if (row0 < M)
                    *(float2*)(C + (size_t)row0 * N + gn) = make_float2(v0, v1);
                if (row0 + 8 < M)
                    *(float2*)(C + (size_t)(row0 + 8) * N + gn) = make_float2(v2, v3);
            }
        }
    }
}

// ---------------- MSDA v5: 8 heads/warp, 16B gathers, HFMA2 blend ------------
__global__ __launch_bounds__(256)
void msda_h_kernel(const __half2* __restrict__ value,
                   const float* __restrict__ qk,
                   const float* __restrict__ ref,
                   __half2* __restrict__ out)
{
    constexpr int kH[4]  = {100, 50, 25, 13};
    constexpr int kW[4]  = {100, 50, 25, 13};
    constexpr int kSt[4] = {0, 10000, 12500, 13125};

    int gwarp = (blockIdx.x * blockDim.x + threadIdx.x) >> 5;
    int lane  = threadIdx.x & 31;
    if (gwarp >= B_SZ * S_TOTAL) return;

    const int bq = gwarp;
    const int b  = (bq >= S_TOTAL) ? 1 : 0;
    const int h  = lane >> 2;
    const int q  = lane & 3;

    float4 lg = __ldg((const float4*)(qk + (size_t)bq * 384 + 256 + h * 16 + q * 4));
    float m = fmaxf(fmaxf(lg.x, lg.y), fmaxf(lg.z, lg.w));
    m = fmaxf(m, __shfl_xor_sync(0xffffffffu, m, 1));
    m = fmaxf(m, __shfl_xor_sync(0xffffffffu, m, 2));
    float e0 = __expf(lg.x - m), e1 = __expf(lg.y - m);
    float e2 = __expf(lg.z - m), e3 = __expf(lg.w - m);
    float ssum = e0 + e1 + e2 + e3;
    ssum += __shfl_xor_sync(0xffffffffu, ssum, 1);
    ssum += __shfl_xor_sync(0xffffffffu, ssum, 2);
    float inv = 1.f / ssum;
    float aw[4] = {e0 * inv, e1 * inv, e2 * inv, e3 * inv};

    const float4* offp = (const float4*)(qk + (size_t)bq * 384 + h * 32 + q * 8);
    float4 of0 = __ldg(offp);
    float4 of1 = __ldg(offp + 1);
    float offx[4] = {of0.x, of0.z, of1.x, of1.z};
    float offy[4] = {of0.y, of0.w, of1.y, of1.w};

    const float* refp = ref + (size_t)bq * (NL * 2);

    float2 acc[4];
    #pragma unroll
    for (int i = 0; i < 4; i++) acc[i] = make_float2(0.f, 0.f);

    #pragma unroll
    for (int l = 0; l < NL; l++) {
        const int H_ = kH[l], W_ = kW[l];
        const float fW = (float)W_, fH = (float)H_;
        const float invW = 1.f / fW, invH = 1.f / fH;
        float refx = __ldg(refp + l * 2 + 0);
        float refy = __ldg(refp + l * 2 + 1);
        const uint4* vbase = (const uint4*)(value + ((size_t)(b * S_TOTAL + kSt[l])) * 128 + h * 16 + q * 4);
        const int srclane = (lane & 28) | l;

        #pragma unroll
        for (int p = 0; p < NP; p++) {
            float w16 = __shfl_sync(0xffffffffu, aw[p],   srclane);
            float ox  = __shfl_sync(0xffffffffu, offx[p], srclane);
            float oy  = __shfl_sync(0xffffffffu, offy[p], srclane);

            float x = (refx + ox * invW) * fW - 0.5f;
            float y = (refy + oy * invH) * fH - 0.5f;
            float x0f = floorf(x), y0f = floorf(y);
            int x0 = (int)x0f, y0 = (int)y0f;
            float fx = x - x0f, fy = y - y0f;

            float mx0 = ((unsigned)x0     < (unsigned)W_) ? 1.f : 0.f;
            float mx1 = ((unsigned)(x0+1) < (unsigned)W_) ? 1.f : 0.f;
            float my0 = ((unsigned)y0     < (unsigned)H_) ? 1.f : 0.f;
            float my1 = ((unsigned)(y0+1) < (unsigned)H_) ? 1.f : 0.f;

            float gx1 = fx * mx1, gx0 = (1.f - fx) * mx0;
            float gy1 = fy * my1, gy0 = (1.f - fy) * my0;
            float w00 = gx0 * gy0 * w16, w10 = gx1 * gy0 * w16;
            float w01 = gx0 * gy1 * w16, w11 = gx1 * gy1 * w16;

            __half2 hw00 = __float2half2_rn(w00);
            __half2 hw10 = __float2half2_rn(w10);
            __half2 hw01 = __float2half2_rn(w01);
            __half2 hw11 = __float2half2_rn(w11);

            int cx0 = min(max(x0, 0), W_ - 1);
            int cx1 = min(max(x0 + 1, 0), W_ - 1);
            int cy0 = min(max(y0, 0), H_ - 1);
            int cy1 = min(max(y0 + 1, 0), H_ - 1);
            int r0 = cy0 * W_, r1 = cy1 * W_;

            uint4 u00 = __ldg(vbase + (size_t)(r0 + cx0) * 32);
            uint4 u10 = __ldg(vbase + (size_t)(r0 + cx1) * 32);
            uint4 u01 = __ldg(vbase + (size_t)(r1 + cx0) * 32);
            uint4 u11 = __ldg(vbase + (size_t)(r1 + cx1) * 32);

            const unsigned* p00 = &u00.x;
            const unsigned* p10 = &u10.x;
            const unsigned* p01 = &u01.x;
            const unsigned* p11 = &u11.x;
            #pragma unroll
            for (int j = 0; j < 4; j++) {
                __half2 s = __hmul2(hw00, *(const __half2*)&p00[j]);
                s = __hfma2(hw10, *(const __half2*)&p10[j], s);
                s = __hfma2(hw01, *(const __half2*)&p01[j], s);
                s = __hfma2(hw11, *(const __half2*)&p11[j], s);
                float2 f = __half22float2(s);
                acc[j].x += f.x;
                acc[j].y += f.y;
            }
        }
    }

    __half2 o[4];
    #pragma unroll
    for (int j = 0; j < 4; j++) o[j] = __floats2half2_rn(acc[j].x, acc[j].y);
    *(uint4*)(out + (size_t)bq * 128 + h * 16 + q * 4) = *(uint4*)o;
}

// -------- residual add + LayerNorm: one WARP per row, fp32 + fp16 out --------
__global__ __launch_bounds__(256)
void add_ln_kernel(const float* __restrict__ xin,
                   const float* __restrict__ r,
                   const float* __restrict__ g,
                   const float* __restrict__ bt,
                   float* __restrict__ xout,
                   __half* __restrict__ xout16)
{
    int gwarp = (blockIdx.x * blockDim.x + threadIdx.x) >> 5;
    int lane  = threadIdx.x & 31;
    if (gwarp >= M_TOTAL) return;
    const size_t base = (size_t)gwarp * 256 + lane * 8;

    float4 a0 = *(const float4*)(xin + base);
    float4 a1 = *(const float4*)(xin + base + 4);
    float4 r0 = *(const float4*)(r + base);
    float4 r1 = *(const float4*)(r + base + 4);
    float v[8] = {a0.x + r0.x, a0.y + r0.y, a0.z + r0.z, a0.w + r0.w,
                  a1.x + r1.x, a1.y + r1.y, a1.z + r1.z, a1.w + r1.w};

    float s1 = 0.f, s2 = 0.f;
    #pragma unroll
    for (int i = 0; i < 8; i++) { s1 += v[i]; s2 = fmaf(v[i], v[i], s2); }
    #pragma unroll
    for (int o = 16; o > 0; o >>= 1) {
        s1 += __shfl_xor_sync(0xffffffffu, s1, o);
        s2 += __shfl_xor_sync(0xffffffffu, s2, o);
    }
    float mean = s1 * (1.f / 256.f);
    float var  = s2 * (1.f / 256.f) - mean * mean;
    float inv  = rsqrtf(var + 1e-5f);

    float4 g0 = *(const float4*)(g + lane * 8);
    float4 g1 = *(const float4*)(g + lane * 8 + 4);
    float4 b0 = *(const float4*)(bt + lane * 8);
    float4 b1 = *(const float4*)(bt + lane * 8 + 4);
    float gg[8] = {g0.x, g0.y, g0.z, g0.w, g1.x, g1.y, g1.z, g1.w};
    float bb[8] = {b0.x, b0.y, b0.z, b0.w, b1.x, b1.y, b1.z, b1.w};

    float o[8];
    #pragma unroll
    for (int i = 0; i < 8; i++) o[i] = (v[i] - mean) * inv * gg[i] + bb[i];

    *(float4*)(xout + base)     = make_float4(o[0], o[1], o[2], o[3]);
    *(float4*)(xout + base + 4) = make_float4(o[4], o[5], o[6], o[7]);
    __half2 h[4] = {__floats2half2_rn(o[0], o[1]), __floats2half2_rn(o[2], o[3]),
                    __floats2half2_rn(o[4], o[5]), __floats2half2_rn(o[6], o[7])};
    *(uint4*)(xout16 + base) = *(uint4*)h;
}

// -----------------------------------------------------------------------------
extern "C" void kernel_launch(void* const* d_in, const int* in_sizes, int n_in,
                              void* d_out, int out_size)
{
    const float* src    = (const float*)d_in[0];
    const float* vr     = (const float*)d_in[2];
    const float* W_off  = (const float*)d_in[3];
    const float* b_off  = (const float*)d_in[4];
    const float* W_attn = (const float*)d_in[5];
    const float* b_attn = (const float*)d_in[6];
    const float* W_val  = (const float*)d_in[7];
    const float* b_val  = (const float*)d_in[8];
    const float* W_out  = (const float*)d_in[9];
    const float* b_out  = (const float*)d_in[10];
    const float* ln1_g  = (const float*)d_in[11];
    const float* ln1_b  = (const float*)d_in[12];
    const float* W1     = (const float*)d_in[13];
    const float* b1     = (const float*)d_in[14];
    const float* W2     = (const float*)d_in[15];
    const float* b2     = (const float*)d_in[16];
    const float* ln2_g  = (const float*)d_in[17];
    const float* ln2_b  = (const float*)d_in[18];

    __half2 *valueh, *msda16;
    __half *x16, *hid16, *wvqk16, *wout16, *w1_16, *w2_16;
    float *qk, *bvqk, *tmp, *xb, *refp;
    cudaGetSymbolAddress((void**)&valueh,  g_value_h);
    cudaGetSymbolAddress((void**)&msda16,  g_msda16);
    cudaGetSymbolAddress((void**)&x16,     g_x16);
    cudaGetSymbolAddress((void**)&hid16,   g_hid16);
    cudaGetSymbolAddress((void**)&wvqk16,  g_wvqk16);
    cudaGetSymbolAddress((void**)&wout16,  g_wout16);
    cudaGetSymbolAddress((void**)&w1_16,   g_w1_16);
    cudaGetSymbolAddress((void**)&w2_16,   g_w2_16);
    cudaGetSymbolAddress((void**)&qk,    g_qk);
    cudaGetSymbolAddress((void**)&bvqk,  g_bvqk);
    cudaGetSymbolAddress((void**)&tmp,   g_tmp);
    cudaGetSymbolAddress((void**)&xb,    g_x);
    cudaGetSymbolAddress((void**)&refp,  g_ref);

    cudaFuncSetAttribute(gemm_tc_kernel<0>, cudaFuncAttributeMaxDynamicSharedMemorySize, SMEM_BYTES);
    cudaFuncSetAttribute(gemm_tc_kernel<1>, cudaFuncAttributeMaxDynamicSharedMemorySize, SMEM_BYTES);
    cudaFuncSetAttribute(gemm_tc_kernel<2>, cudaFuncAttributeMaxDynamicSharedMemorySize, SMEM_BYTES);
    cudaFuncSetAttribute(gemm_tc_kernel<3>, cudaFuncAttributeMaxDynamicSharedMemorySize, SMEM_BYTES);

    const int M = M_TOTAL;
    const int GM = (M + 127) / 128;   // 208

    cvt_all_kernel<<<(CVT_C9 + 255) / 256, 256>>>(
        W_val, W_off, W_attn, W_out, W1, W2, src, b_val, b_off, b_attn,
        wvqk16, wout16, w1_16, w2_16, x16, bvqk);

    ref_kernel<<<(M + 255) / 256, 256>>>(vr, refp);

    for (int i = 0; i < NUM_LAYERS; i++) {
        const float* xin = (i == 0) ? src : xb;   // fp32 residual source

        // fused value + off + attn projection (N=640, split epilogue)
        gemm_tc_kernel<3><<<dim3(5, GM), 256, SMEM_BYTES>>>(
            x16, wvqk16 + (size_t)i * 256 * 640, bvqk + i * 640,
            qk, valueh, M, 640, 256);

        msda_h_kernel<<<(M * 32 + 255) / 256, 256>>>(valueh, qk, refp, msda16);

        gemm_tc_kernel<0><<<dim3(2, GM), 256, SMEM_BYTES>>>(
            (const __half*)msda16, wout16 + (size_t)i * 256 * 256, b_out + i * 256,
            tmp, nullptr, M, 256, 256);
        add_ln_kernel<<<(M * 32 + 255) / 256, 256>>>(xin, tmp, ln1_g + i * 256, ln1_b + i * 256, xb, x16);

        gemm_tc_kernel<1><<<dim3(8, GM), 256, SMEM_BYTES>>>(
            x16, w1_16 + (size_t)i * 256 * 1024, b1 + i * 1024,
            nullptr, (__half2*)hid16, M, 1024, 256);
        gemm_tc_kernel<0><<<dim3(2, GM), 256, SMEM_BYTES>>>(
            hid16, w2_16 + (size_t)i * 1024 * 256, b2 + i * 256,
            tmp, nullptr, M, 256, 1024);

        float* lnout = (i == NUM_LAYERS - 1) ? (float*)d_out : xb;
        add_ln_kernel<<<(M * 32 + 255) / 256, 256>>>(xb, tmp, ln2_g + i * 256, ln2_b + i * 256, lnout, x16);
    }
}